// round 8
// baseline (speedup 1.0000x reference)
#include <cuda_runtime.h>
#include <cstdint>

// ---------------- problem dims ----------------
#define Tdim 2048
#define Bdim 64
#define Kdim 512
#define Odim 512

// ---------------- tiling ----------------
#define TSTRIP 32            // timesteps per strip (CTA)
#define NSTRIPS 64           // 2048/32
#define MITERS 16            // 2 timesteps (=128 M rows) per iter
#define KT 32                // K per stage (floats)
#define KTILES 16            // 512/32
#define NTOT (MITERS*KTILES) // 256 stages per CTA
#define STR 36               // smem row stride in floats (32 + 4 pad, conflict-free)
#define STAGE_BYTES (128*STR*4)   // 18432 per operand per stage
#define NSTAGE 4
#define NTHREADS 512

// smem layout (bytes)
#define SM_A 0
#define SM_B (NSTAGE*STAGE_BYTES)                  // 73728
#define SM_TOTAL (2*NSTAGE*STAGE_BYTES)            // 147456

// ---------------- device scratch ----------------
// combined K-major weights: row n = 2*o + s (s=0:g, s=1:h), cols k
__device__ float g_wT[2 * Odim * Kdim];
__device__ float g_As[NSTRIPS * Bdim * Odim];
__device__ float g_Bs[NSTRIPS * Bdim * Odim];

// ---------------- helpers ----------------
__device__ __forceinline__ uint32_t smem_u32(const void* p) {
    uint32_t a;
    asm("{ .reg .u64 t; cvta.to.shared.u64 t, %1; cvt.u32.u64 %0, t; }" : "=r"(a) : "l"(p));
    return a;
}
__device__ __forceinline__ void cp16(uint32_t dst, const float* src) {
    asm volatile("cp.async.cg.shared.global [%0], [%1], 16;" :: "r"(dst), "l"(src));
}
__device__ __forceinline__ void cp_commit() { asm volatile("cp.async.commit_group;" ::: "memory"); }
__device__ __forceinline__ float tanha(float x) {
    float y; asm("tanh.approx.f32 %0, %1;" : "=f"(y) : "f"(x)); return y;
}

// ---------------- weight prep: g,h -> interleaved K-major g_wT ----------------
__global__ void prep_w(const float* __restrict__ g, const float* __restrict__ h)
{
    __shared__ float t[32][33];
    const int s = blockIdx.z;
    const float* src = s ? h : g;
    const int ob = blockIdx.x * 32, kb = blockIdx.y * 32;
    #pragma unroll
    for (int i = 0; i < 32; i += 8)
        t[threadIdx.y + i][threadIdx.x] = src[(size_t)(kb + threadIdx.y + i) * Odim + ob + threadIdx.x];
    __syncthreads();
    #pragma unroll
    for (int i = 0; i < 32; i += 8)
        g_wT[(size_t)(2 * (ob + threadIdx.y + i) + s) * Kdim + kb + threadIdx.x] = t[threadIdx.x][threadIdx.y + i];
}

// ---------------- stage loader ----------------
__device__ __forceinline__ void load_stage(uint32_t sbase, const float* __restrict__ x,
                                           int strip, int n_base, int ktg, int tid)
{
    const int stage = ktg & 3;
    const int iter = ktg >> 4, kt = ktg & 15;
    const int kbase = kt * KT;
    const int t0 = strip * TSTRIP + iter * 2;
    const uint32_t aB = sbase + SM_A + stage * STAGE_BYTES;
    const uint32_t bB = sbase + SM_B + stage * STAGE_BYTES;
    #pragma unroll
    for (int j = 0; j < 2; j++) {                 // A: 128 rows, row = 2b + tp
        int c = tid + NTHREADS * j;
        int row = c >> 3, seg = c & 7;
        int m = (t0 + (row & 1)) * Bdim + (row >> 1);
        cp16(aB + (row * STR + seg * 4) * 4, x + (size_t)m * Kdim + kbase + seg * 4);
    }
    #pragma unroll
    for (int j = 0; j < 2; j++) {                 // B: 128 rows = interleaved (G,H) cols
        int c = tid + NTHREADS * j;
        int row = c >> 3, seg = c & 7;
        cp16(bB + (row * STR + seg * 4) * 4,
             g_wT + (size_t)(n_base + row) * Kdim + kbase + seg * 4);
    }
}

// ---------------- fragment loader (conflict-free: grp*4+tig banks) ----------------
__device__ __forceinline__ void load_frags(const float* __restrict__ xs,
                                           const float* __restrict__ bs, int kk,
                                           int wm, int wn, int grp, int tig,
                                           uint32_t a[2][4], uint32_t b[4][2])
{
    #pragma unroll
    for (int mi = 0; mi < 2; mi++) {
        int r0 = wm + mi * 16 + grp;
        a[mi][0] = __float_as_uint(xs[r0 * STR + kk + tig]);
        a[mi][1] = __float_as_uint(xs[(r0 + 8) * STR + kk + tig]);
        a[mi][2] = __float_as_uint(xs[r0 * STR + kk + tig + 4]);
        a[mi][3] = __float_as_uint(xs[(r0 + 8) * STR + kk + tig + 4]);
    }
    #pragma unroll
    for (int ni = 0; ni < 4; ni++) {
        int n = wn + ni * 8 + grp;
        b[ni][0] = __float_as_uint(bs[n * STR + kk + tig]);
        b[ni][1] = __float_as_uint(bs[n * STR + kk + tig + 4]);
    }
}

// ---------------- main kernel ----------------
__global__ void __launch_bounds__(NTHREADS, 1)
rnn_gemm_scan(const float* __restrict__ x,  const float* __restrict__ gb,
              const float* __restrict__ hb, const float* __restrict__ r,
              const float* __restrict__ rb)
{
    extern __shared__ float smf[];
    const uint32_t sbase = smem_u32(smf);
    const int tid = threadIdx.x, lane = tid & 31, wid = tid >> 5;
    const int o_base = blockIdx.x * 64;       // 64 outputs per CTA (N=128 interleaved)
    const int strip  = blockIdx.y;
    const int wm = (wid & 3) * 32;            // 4 warps in M
    const int wn = (wid >> 2) * 32;           // 4 warps in N
    const int grp = lane >> 2, tig = lane & 3;
    const int tp = grp & 1;                   // timestep parity of this thread's rows

    // per-thread output set: ol = wn/2 + ni*4 + tig
    float gbv[4], hbv[4], rv[4], rbv[4];
    #pragma unroll
    for (int ni = 0; ni < 4; ni++) {
        int o = o_base + (wn >> 1) + ni * 4 + tig;
        gbv[ni] = gb[o]; hbv[ni] = hb[o]; rv[ni] = r[o]; rbv[ni] = rb[o];
    }
    // register-resident scan state [mi][hl][ni]
    float sA[2][2][4], sB[2][2][4];
    #pragma unroll
    for (int mi = 0; mi < 2; mi++)
        #pragma unroll
        for (int hl = 0; hl < 2; hl++)
            #pragma unroll
            for (int ni = 0; ni < 4; ni++) { sA[mi][hl][ni] = 1.0f; sB[mi][hl][ni] = 0.0f; }

    const int n_base = o_base * 2;

    // pipeline prologue: 3 stages in flight
    load_stage(sbase, x, strip, n_base, 0, tid); cp_commit();
    load_stage(sbase, x, strip, n_base, 1, tid); cp_commit();
    load_stage(sbase, x, strip, n_base, 2, tid); cp_commit();

    for (int iter = 0; iter < MITERS; iter++) {
        float acc[2][4][4];
        #pragma unroll
        for (int mi = 0; mi < 2; mi++)
            #pragma unroll
            for (int ni = 0; ni < 4; ni++)
                #pragma unroll
                for (int e = 0; e < 4; e++) acc[mi][ni][e] = 0.0f;

        for (int kt = 0; kt < KTILES; kt++) {
            const int ktg = iter * KTILES + kt;
            asm volatile("cp.async.wait_group 2;" ::: "memory");
            __syncthreads();                       // stage ktg ready; stage ktg-1 fully consumed
            if (ktg + 3 < NTOT) load_stage(sbase, x, strip, n_base, ktg + 3, tid);
            cp_commit();                           // always commit (keeps group math exact)

            const float* xs = smf + (SM_A / 4) + (ktg & 3) * (STAGE_BYTES / 4);
            const float* bs = smf + (SM_B / 4) + (ktg & 3) * (STAGE_BYTES / 4);

            uint32_t a[2][2][4], b[2][4][2];
            load_frags(xs, bs, 0, wm, wn, grp, tig, a[0], b[0]);
            #pragma unroll
            for (int kk4 = 0; kk4 < 4; kk4++) {
                const int cur = kk4 & 1;
                if (kk4 < 3)
                    load_frags(xs, bs, (kk4 + 1) * 8, wm, wn, grp, tig, a[cur ^ 1], b[cur ^ 1]);
                #pragma unroll
                for (int mi = 0; mi < 2; mi++)
                    #pragma unroll
                    for (int ni = 0; ni < 4; ni++)
                        asm volatile(
                            "mma.sync.aligned.m16n8k8.row.col.f32.tf32.tf32.f32 "
                            "{%0,%1,%2,%3},{%4,%5,%6,%7},{%8,%9},{%0,%1,%2,%3};"
                            : "+f"(acc[mi][ni][0]), "+f"(acc[mi][ni][1]),
                              "+f"(acc[mi][ni][2]), "+f"(acc[mi][ni][3])
                            : "r"(a[cur][mi][0]), "r"(a[cur][mi][1]),
                              "r"(a[cur][mi][2]), "r"(a[cur][mi][3]),
                              "r"(b[cur][ni][0]), "r"(b[cur][ni][1]));
            }
        }

        // ---- register epilogue: gate + pair-combine (shfl_xor 4) + compose ----
        const float t = (float)(strip * TSTRIP + iter * 2 + tp) * (1.0f / 2048.0f);
        float rt[4];
        #pragma unroll
        for (int ni = 0; ni < 4; ni++)
            rt[ni] = 1.0f + tanha(0.5f * (t * rv[ni] + rbv[ni]));   // 2*sigmoid(v)

        #pragma unroll
        for (int mi = 0; mi < 2; mi++)
            #pragma unroll
            for (int ni = 0; ni < 4; ni++)
                #pragma unroll
                for (int hl = 0; hl < 2; hl++) {
                    float zg = acc[mi][ni][hl * 2 + 0];
                    float zh = acc[mi][ni][hl * 2 + 1];
                    float G = rt[ni] * (0.5f + 0.5f * tanha(0.5f * (zg + gbv[ni])));
                    float H = rt[ni] * tanha(zh + hbv[ni]);
                    float Gp = __shfl_xor_sync(0xffffffffu, G, 4);
                    float Hp = __shfl_xor_sync(0xffffffffu, H, 4);
                    // on tp==0 lanes: own=(G0,H0), partner=(G1,H1)
                    float A2 = Gp * G;
                    float B2 = Gp * H + Hp;
                    sB[mi][hl][ni] = A2 * sB[mi][hl][ni] + B2;
                    sA[mi][hl][ni] *= A2;
                }
    }

    // drain remaining async groups before exit writes
    asm volatile("cp.async.wait_group 0;" ::: "memory");

    // ---- write strip transform (tp==0 lanes own valid state) ----
    if (tp == 0) {
        #pragma unroll
        for (int mi = 0; mi < 2; mi++)
            #pragma unroll
            for (int hl = 0; hl < 2; hl++)
                #pragma unroll
                for (int ni = 0; ni < 4; ni++) {
                    int bb = (wm >> 1) + mi * 8 + hl * 4 + (grp >> 1);
                    int o  = o_base + (wn >> 1) + ni * 4 + tig;
                    size_t gi = (size_t)(strip * Bdim + bb) * Odim + o;
                    g_As[gi] = sA[mi][hl][ni];
                    g_Bs[gi] = sB[mi][hl][ni];
                }
    }
}

// ---------------- strip combine ----------------
__global__ void rnn_combine(float* __restrict__ out)
{
    int idx = blockIdx.x * 256 + threadIdx.x;   // = b*512 + o
    float y = 0.0f;
    #pragma unroll 8
    for (int s = 0; s < NSTRIPS; s++)
        y = g_As[s * (Bdim * Odim) + idx] * y + g_Bs[s * (Bdim * Odim) + idx];
    out[idx] = y;
}

extern "C" void kernel_launch(void* const* d_in, const int* in_sizes, int n_in,
                              void* d_out, int out_size)
{
    const float* x  = (const float*)d_in[0];
    const float* g  = (const float*)d_in[1];
    const float* gb = (const float*)d_in[2];
    const float* h  = (const float*)d_in[3];
    const float* hb = (const float*)d_in[4];
    const float* r  = (const float*)d_in[5];
    const float* rb = (const float*)d_in[6];

    cudaFuncSetAttribute((const void*)rnn_gemm_scan,
                         cudaFuncAttributeMaxDynamicSharedMemorySize, SM_TOTAL);

    prep_w<<<dim3(16, 16, 2), dim3(32, 8)>>>(g, h);
    rnn_gemm_scan<<<dim3(8, NSTRIPS), NTHREADS, SM_TOTAL>>>(x, gb, hb, r, rb);
    rnn_combine<<<(Bdim * Odim) / 256, 256>>>((float*)d_out);
}

// round 10
// speedup vs baseline: 1.8099x; 1.8099x over previous
#include <cuda_runtime.h>
#include <cuda_fp16.h>
#include <cstdint>

// ---------------- problem dims ----------------
#define Tdim 2048
#define Bdim 64
#define Kdim 512
#define Odim 512

// ---------------- tiling ----------------
#define TSTRIP 32            // timesteps per strip (CTA)
#define NSTRIPS 64           // 2048/32
#define MITERS 16            // 2 timesteps (=128 M rows) per iter
#define KT 64                // K per stage (halves)
#define KTILES 8             // 512/64
#define NTOT (MITERS*KTILES) // 128 stages per CTA
#define STR 72               // smem row stride in halves (64 + 8 pad) = 144B
#define STAGE_BYTES (128*STR*2)   // 18432 per operand per stage
#define NSTAGE 4
#define NTHREADS 256

// smem layout (bytes)
#define SM_A 0
#define SM_B (NSTAGE*STAGE_BYTES)                  // 73728
#define SM_TOTAL (2*NSTAGE*STAGE_BYTES)            // 147456

// ---------------- device scratch ----------------
__device__ __half g_xh[(size_t)Tdim * Bdim * Kdim];     // fp16 copy of x (128MB)
__device__ __half g_wTh[2 * Odim * Kdim];               // K-major interleaved weights, n=2o+s
__device__ float  g_As[NSTRIPS * Bdim * Odim];
__device__ float  g_Bs[NSTRIPS * Bdim * Odim];

// ---------------- helpers ----------------
__device__ __forceinline__ uint32_t smem_u32(const void* p) {
    uint32_t a;
    asm("{ .reg .u64 t; cvta.to.shared.u64 t, %1; cvt.u32.u64 %0, t; }" : "=r"(a) : "l"(p));
    return a;
}
__device__ __forceinline__ void cp16(uint32_t dst, const void* src) {
    asm volatile("cp.async.cg.shared.global [%0], [%1], 16;" :: "r"(dst), "l"(src));
}
__device__ __forceinline__ void cp_commit() { asm volatile("cp.async.commit_group;" ::: "memory"); }
__device__ __forceinline__ float tanha(float x) {
    float y; asm("tanh.approx.f32 %0, %1;" : "=f"(y) : "f"(x)); return y;
}
__device__ __forceinline__ uint32_t ldh2(const __half* p) {
    return *reinterpret_cast<const uint32_t*>(p);
}

// ---------------- prep: x (f32) -> g_xh (fp16) ----------------
__global__ void prep_x(const float* __restrict__ x)
{
    size_t i = ((size_t)blockIdx.x * 256 + threadIdx.x) * 4;
    float4 v = *reinterpret_cast<const float4*>(x + i);
    __half2 lo = __floats2half2_rn(v.x, v.y);
    __half2 hi = __floats2half2_rn(v.z, v.w);
    *reinterpret_cast<uint2*>(g_xh + i) =
        make_uint2(*reinterpret_cast<uint32_t*>(&lo), *reinterpret_cast<uint32_t*>(&hi));
}

// ---------------- prep: g,h -> interleaved K-major fp16 g_wTh ----------------
__global__ void prep_w(const float* __restrict__ g, const float* __restrict__ h)
{
    __shared__ float t[32][33];
    const int s = blockIdx.z;
    const float* src = s ? h : g;
    const int ob = blockIdx.x * 32, kb = blockIdx.y * 32;
    #pragma unroll
    for (int i = 0; i < 32; i += 8)
        t[threadIdx.y + i][threadIdx.x] = src[(size_t)(kb + threadIdx.y + i) * Odim + ob + threadIdx.x];
    __syncthreads();
    #pragma unroll
    for (int i = 0; i < 32; i += 8)
        g_wTh[(size_t)(2 * (ob + threadIdx.y + i) + s) * Kdim + kb + threadIdx.x] =
            __float2half_rn(t[threadIdx.x][threadIdx.y + i]);
}

// ---------------- stage loader (1024 x 16B chunks per operand) ----------------
__device__ __forceinline__ void load_stage(uint32_t sbase, int strip, int n_base,
                                           int ktg, int tid)
{
    const int stage = ktg & 3;
    const int iter = ktg >> 3, kt = ktg & 7;
    const int kbase = kt * KT;
    const int t0 = strip * TSTRIP + iter * 2;
    const uint32_t aB = sbase + SM_A + stage * STAGE_BYTES;
    const uint32_t bB = sbase + SM_B + stage * STAGE_BYTES;
    #pragma unroll
    for (int j = 0; j < 4; j++) {                 // A: 128 rows (row = 2b+tp) x 64 halves
        int c = tid + NTHREADS * j;
        int row = c >> 3, seg = c & 7;
        int m = (t0 + (row & 1)) * Bdim + (row >> 1);
        cp16(aB + row * (STR * 2) + seg * 16,
             g_xh + (size_t)m * Kdim + kbase + seg * 8);
    }
    #pragma unroll
    for (int j = 0; j < 4; j++) {                 // B: 128 rows = interleaved (G,H) cols
        int c = tid + NTHREADS * j;
        int row = c >> 3, seg = c & 7;
        cp16(bB + row * (STR * 2) + seg * 16,
             g_wTh + (size_t)(n_base + row) * Kdim + kbase + seg * 8);
    }
}

// ---------------- fragment loader (all-distinct-bank half2 loads) ----------------
__device__ __forceinline__ void load_frags(const __half* __restrict__ xs,
                                           const __half* __restrict__ bs, int kk,
                                           int wm, int wn, int grp, int tig,
                                           uint32_t a[2][4], uint32_t b[8][2])
{
    #pragma unroll
    for (int mi = 0; mi < 2; mi++) {
        int r0 = wm + mi * 16 + grp;
        a[mi][0] = ldh2(xs + r0 * STR + kk + tig * 2);
        a[mi][1] = ldh2(xs + (r0 + 8) * STR + kk + tig * 2);
        a[mi][2] = ldh2(xs + r0 * STR + kk + tig * 2 + 8);
        a[mi][3] = ldh2(xs + (r0 + 8) * STR + kk + tig * 2 + 8);
    }
    #pragma unroll
    for (int ni = 0; ni < 8; ni++) {
        int n = wn + ni * 8 + grp;
        b[ni][0] = ldh2(bs + n * STR + kk + tig * 2);
        b[ni][1] = ldh2(bs + n * STR + kk + tig * 2 + 8);
    }
}

// ---------------- main kernel ----------------
__global__ void __launch_bounds__(NTHREADS, 1)
rnn_gemm_scan(const float* __restrict__ gb, const float* __restrict__ hb,
              const float* __restrict__ r,  const float* __restrict__ rb)
{
    extern __shared__ __half smh[];
    const uint32_t sbase = smem_u32(smh);
    const int tid = threadIdx.x, lane = tid & 31, wid = tid >> 5;
    const int o_base = blockIdx.x * 64;       // 64 outputs per CTA (N=128 interleaved)
    const int strip  = blockIdx.y;
    const int wm = (wid & 3) * 32;            // 4 warps in M
    const int wn = (wid >> 2) * 64;           // 2 warps in N
    const int grp = lane >> 2, tig = lane & 3;
    const int tp = grp & 1;                   // timestep parity of this thread's rows

    float gbv[8], hbv[8], rv[8], rbv[8];
    #pragma unroll
    for (int ni = 0; ni < 8; ni++) {
        int o = o_base + (wn >> 1) + ni * 4 + tig;
        gbv[ni] = gb[o]; hbv[ni] = hb[o]; rv[ni] = r[o]; rbv[ni] = rb[o];
    }
    // register-resident scan state [mi][hl][ni]
    float sA[2][2][8], sB[2][2][8];
    #pragma unroll
    for (int mi = 0; mi < 2; mi++)
        #pragma unroll
        for (int hl = 0; hl < 2; hl++)
            #pragma unroll
            for (int ni = 0; ni < 8; ni++) { sA[mi][hl][ni] = 1.0f; sB[mi][hl][ni] = 0.0f; }

    const int n_base = o_base * 2;

    load_stage(sbase, strip, n_base, 0, tid); cp_commit();
    load_stage(sbase, strip, n_base, 1, tid); cp_commit();
    load_stage(sbase, strip, n_base, 2, tid); cp_commit();

    for (int iter = 0; iter < MITERS; iter++) {
        float acc[2][8][4];
        #pragma unroll
        for (int mi = 0; mi < 2; mi++)
            #pragma unroll
            for (int ni = 0; ni < 8; ni++)
                #pragma unroll
                for (int e = 0; e < 4; e++) acc[mi][ni][e] = 0.0f;

        for (int kt = 0; kt < KTILES; kt++) {
            const int ktg = iter * KTILES + kt;
            asm volatile("cp.async.wait_group 2;" ::: "memory");
            __syncthreads();
            if (ktg + 3 < NTOT) load_stage(sbase, strip, n_base, ktg + 3, tid);
            cp_commit();

            const __half* xs = smh + (SM_A / 2) + (ktg & 3) * (STAGE_BYTES / 2);
            const __half* bs = smh + (SM_B / 2) + (ktg & 3) * (STAGE_BYTES / 2);

            uint32_t a[2][2][4], b[2][8][2];
            load_frags(xs, bs, 0, wm, wn, grp, tig, a[0], b[0]);
            #pragma unroll
            for (int kk4 = 0; kk4 < 4; kk4++) {       // 4 x k16 steps
                const int cur = kk4 & 1;
                if (kk4 < 3)
                    load_frags(xs, bs, (kk4 + 1) * 16, wm, wn, grp, tig, a[cur ^ 1], b[cur ^ 1]);
                #pragma unroll
                for (int mi = 0; mi < 2; mi++)
                    #pragma unroll
                    for (int ni = 0; ni < 8; ni++)
                        asm volatile(
                            "mma.sync.aligned.m16n8k16.row.col.f32.f16.f16.f32 "
                            "{%0,%1,%2,%3},{%4,%5,%6,%7},{%8,%9},{%0,%1,%2,%3};"
                            : "+f"(acc[mi][ni][0]), "+f"(acc[mi][ni][1]),
                              "+f"(acc[mi][ni][2]), "+f"(acc[mi][ni][3])
                            : "r"(a[cur][mi][0]), "r"(a[cur][mi][1]),
                              "r"(a[cur][mi][2]), "r"(a[cur][mi][3]),
                              "r"(b[cur][ni][0]), "r"(b[cur][ni][1]));
            }
        }

        // ---- register epilogue: gate + pair-combine (shfl_xor 4) + compose ----
        const float t = (float)(strip * TSTRIP + iter * 2 + tp) * (1.0f / 2048.0f);
        float rt[8];
        #pragma unroll
        for (int ni = 0; ni < 8; ni++)
            rt[ni] = 1.0f + tanha(0.5f * (t * rv[ni] + rbv[ni]));   // 2*sigmoid(v)

        #pragma unroll
        for (int mi = 0; mi < 2; mi++)
            #pragma unroll
            for (int ni = 0; ni < 8; ni++)
                #pragma unroll
                for (int hl = 0; hl < 2; hl++) {
                    float zg = acc[mi][ni][hl * 2 + 0];
                    float zh = acc[mi][ni][hl * 2 + 1];
                    float G = rt[ni] * (0.5f + 0.5f * tanha(0.5f * (zg + gbv[ni])));
                    float H = rt[ni] * tanha(zh + hbv[ni]);
                    float Gp = __shfl_xor_sync(0xffffffffu, G, 4);
                    float Hp = __shfl_xor_sync(0xffffffffu, H, 4);
                    float A2 = Gp * G;
                    float B2 = Gp * H + Hp;
                    sB[mi][hl][ni] = A2 * sB[mi][hl][ni] + B2;
                    sA[mi][hl][ni] *= A2;
                }
    }

    asm volatile("cp.async.wait_group 0;" ::: "memory");

    // ---- write strip transform (tp==0 lanes own valid state) ----
    if (tp == 0) {
        #pragma unroll
        for (int mi = 0; mi < 2; mi++)
            #pragma unroll
            for (int hl = 0; hl < 2; hl++)
                #pragma unroll
                for (int ni = 0; ni < 8; ni++) {
                    int bb = (wm >> 1) + mi * 8 + hl * 4 + (grp >> 1);
                    int o  = o_base + (wn >> 1) + ni * 4 + tig;
                    size_t gi = (size_t)(strip * Bdim + bb) * Odim + o;
                    g_As[gi] = sA[mi][hl][ni];
                    g_Bs[gi] = sB[mi][hl][ni];
                }
    }
}

// ---------------- strip combine ----------------
__global__ void rnn_combine(float* __restrict__ out)
{
    int idx = blockIdx.x * 256 + threadIdx.x;   // = b*512 + o
    float y = 0.0f;
    #pragma unroll 8
    for (int s = 0; s < NSTRIPS; s++)
        y = g_As[s * (Bdim * Odim) + idx] * y + g_Bs[s * (Bdim * Odim) + idx];
    out[idx] = y;
}

extern "C" void kernel_launch(void* const* d_in, const int* in_sizes, int n_in,
                              void* d_out, int out_size)
{
    const float* x  = (const float*)d_in[0];
    const float* g  = (const float*)d_in[1];
    const float* gb = (const float*)d_in[2];
    const float* h  = (const float*)d_in[3];
    const float* hb = (const float*)d_in[4];
    const float* r  = (const float*)d_in[5];
    const float* rb = (const float*)d_in[6];

    cudaFuncSetAttribute((const void*)rnn_gemm_scan,
                         cudaFuncAttributeMaxDynamicSharedMemorySize, SM_TOTAL);

    prep_x<<<(Tdim * Bdim * Kdim) / (256 * 4), 256>>>(x);
    prep_w<<<dim3(16, 16, 2), dim3(32, 8)>>>(g, h);
    rnn_gemm_scan<<<dim3(8, NSTRIPS), NTHREADS, SM_TOTAL>>>(gb, hb, r, rb);
    rnn_combine<<<(Bdim * Odim) / 256, 256>>>((float*)d_out);
}

// round 14
// speedup vs baseline: 1.9968x; 1.1032x over previous
#include <cuda_runtime.h>
#include <cuda_fp16.h>
#include <cstdint>

// ---------------- problem dims ----------------
#define Tdim 2048
#define Bdim 64
#define Kdim 512
#define Odim 512

// ---------------- tiling ----------------
#define TSTRIP 16            // timesteps per strip (CTA)
#define NSTRIPS 128          // 2048/16
#define MITERS 8             // 2 timesteps (=128 M rows) per iter
#define KT 64                // K per stage (halves)
#define KTILES 8             // 512/64
#define NTOT (MITERS*KTILES) // 64 stages per CTA
#define STR 72               // smem row stride in halves (64 + 8 pad) = 144B
#define STAGE_BYTES (128*STR*2)   // 18432 per operand per stage
#define NSTAGE 4
#define NTHREADS 256

// smem layout (bytes)
#define SM_A 0
#define SM_B (NSTAGE*STAGE_BYTES)                  // 73728
#define SM_TOTAL (2*NSTAGE*STAGE_BYTES)            // 147456

// ---------------- device scratch ----------------
__device__ __half g_xh[(size_t)Tdim * Bdim * Kdim];     // fp16 copy of x (128MB)
__device__ __half g_wTh[2 * Odim * Kdim];               // K-major interleaved weights, n=2o+s
__device__ float  g_As[NSTRIPS * Bdim * Odim];
__device__ float  g_Bs[NSTRIPS * Bdim * Odim];

// ---------------- helpers ----------------
__device__ __forceinline__ uint32_t smem_u32(const void* p) {
    uint32_t a;
    asm("{ .reg .u64 t; cvta.to.shared.u64 t, %1; cvt.u32.u64 %0, t; }" : "=r"(a) : "l"(p));
    return a;
}
__device__ __forceinline__ void cp16(uint32_t dst, const void* src) {
    asm volatile("cp.async.cg.shared.global [%0], [%1], 16;" :: "r"(dst), "l"(src));
}
__device__ __forceinline__ void cp_commit() { asm volatile("cp.async.commit_group;" ::: "memory"); }
__device__ __forceinline__ float tanha(float x) {
    float y; asm("tanh.approx.f32 %0, %1;" : "=f"(y) : "f"(x)); return y;
}
__device__ __forceinline__ uint32_t ldh2(const __half* p) {
    return *reinterpret_cast<const uint32_t*>(p);
}

// ---------------- prep: x (f32) -> g_xh (fp16) ----------------
__global__ void prep_x(const float* __restrict__ x)
{
    size_t i = ((size_t)blockIdx.x * 256 + threadIdx.x) * 4;
    float4 v = *reinterpret_cast<const float4*>(x + i);
    __half2 lo = __floats2half2_rn(v.x, v.y);
    __half2 hi = __floats2half2_rn(v.z, v.w);
    *reinterpret_cast<uint2*>(g_xh + i) =
        make_uint2(*reinterpret_cast<uint32_t*>(&lo), *reinterpret_cast<uint32_t*>(&hi));
}

// ---------------- prep: g,h -> interleaved K-major fp16 g_wTh ----------------
__global__ void prep_w(const float* __restrict__ g, const float* __restrict__ h)
{
    __shared__ float t[32][33];
    const int s = blockIdx.z;
    const float* src = s ? h : g;
    const int ob = blockIdx.x * 32, kb = blockIdx.y * 32;
    #pragma unroll
    for (int i = 0; i < 32; i += 8)
        t[threadIdx.y + i][threadIdx.x] = src[(size_t)(kb + threadIdx.y + i) * Odim + ob + threadIdx.x];
    __syncthreads();
    #pragma unroll
    for (int i = 0; i < 32; i += 8)
        g_wTh[(size_t)(2 * (ob + threadIdx.y + i) + s) * Kdim + kb + threadIdx.x] =
            __float2half_rn(t[threadIdx.x][threadIdx.y + i]);
}

// ---------------- stage loader (1024 x 16B chunks per operand) ----------------
__device__ __forceinline__ void load_stage(uint32_t sbase, int strip, int n_base,
                                           int ktg, int tid)
{
    const int stage = ktg & 3;
    const int iter = ktg >> 3, kt = ktg & 7;
    const int kbase = kt * KT;
    const int t0 = strip * TSTRIP + iter * 2;
    const uint32_t aB = sbase + SM_A + stage * STAGE_BYTES;
    const uint32_t bB = sbase + SM_B + stage * STAGE_BYTES;
    #pragma unroll
    for (int j = 0; j < 4; j++) {                 // A: 128 rows (row = 2b+tp) x 64 halves
        int c = tid + NTHREADS * j;
        int row = c >> 3, seg = c & 7;
        int m = (t0 + (row & 1)) * Bdim + (row >> 1);
        cp16(aB + row * (STR * 2) + seg * 16,
             g_xh + (size_t)m * Kdim + kbase + seg * 8);
    }
    #pragma unroll
    for (int j = 0; j < 4; j++) {                 // B: 128 rows = interleaved (G,H) cols
        int c = tid + NTHREADS * j;
        int row = c >> 3, seg = c & 7;
        cp16(bB + row * (STR * 2) + seg * 16,
             g_wTh + (size_t)(n_base + row) * Kdim + kbase + seg * 8);
    }
}

// ---------------- fragment loader (all-distinct-bank half2 loads) ----------------
__device__ __forceinline__ void load_frags(const __half* __restrict__ xs,
                                           const __half* __restrict__ bs, int kk,
                                           int wm, int wn, int grp, int tig,
                                           uint32_t a[2][4], uint32_t b[8][2])
{
    #pragma unroll
    for (int mi = 0; mi < 2; mi++) {
        int r0 = wm + mi * 16 + grp;
        a[mi][0] = ldh2(xs + r0 * STR + kk + tig * 2);
        a[mi][1] = ldh2(xs + (r0 + 8) * STR + kk + tig * 2);
        a[mi][2] = ldh2(xs + r0 * STR + kk + tig * 2 + 8);
        a[mi][3] = ldh2(xs + (r0 + 8) * STR + kk + tig * 2 + 8);
    }
    #pragma unroll
    for (int ni = 0; ni < 8; ni++) {
        int n = wn + ni * 8 + grp;
        b[ni][0] = ldh2(bs + n * STR + kk + tig * 2);
        b[ni][1] = ldh2(bs + n * STR + kk + tig * 2 + 8);
    }
}

// ---------------- main kernel ----------------
__global__ void __launch_bounds__(NTHREADS, 1)
rnn_gemm_scan(const float* __restrict__ gb, const float* __restrict__ hb,
              const float* __restrict__ r,  const float* __restrict__ rb)
{
    extern __shared__ __half smh[];
    const uint32_t sbase = smem_u32(smh);
    const int tid = threadIdx.x, lane = tid & 31, wid = tid >> 5;
    const int o_base = blockIdx.x * 64;       // 64 outputs per CTA (N=128 interleaved)
    const int strip  = blockIdx.y;
    const int wm = (wid & 3) * 32;            // 4 warps in M
    const int wn = (wid >> 2) * 64;           // 2 warps in N
    const int grp = lane >> 2, tig = lane & 3;
    const int tp = grp & 1;                   // timestep parity of this thread's rows

    float gbv[8], hbv[8], rv[8], rbv[8];
    #pragma unroll
    for (int ni = 0; ni < 8; ni++) {
        int o = o_base + (wn >> 1) + ni * 4 + tig;
        gbv[ni] = gb[o]; hbv[ni] = hb[o]; rv[ni] = r[o]; rbv[ni] = rb[o];
    }
    // register-resident scan state [mi][hl][ni]
    float sA[2][2][8], sB[2][2][8];
    #pragma unroll
    for (int mi = 0; mi < 2; mi++)
        #pragma unroll
        for (int hl = 0; hl < 2; hl++)
            #pragma unroll
            for (int ni = 0; ni < 8; ni++) { sA[mi][hl][ni] = 1.0f; sB[mi][hl][ni] = 0.0f; }

    const int n_base = o_base * 2;

    load_stage(sbase, strip, n_base, 0, tid); cp_commit();
    load_stage(sbase, strip, n_base, 1, tid); cp_commit();
    load_stage(sbase, strip, n_base, 2, tid); cp_commit();

    for (int iter = 0; iter < MITERS; iter++) {
        float acc[2][8][4];
        #pragma unroll
        for (int mi = 0; mi < 2; mi++)
            #pragma unroll
            for (int ni = 0; ni < 8; ni++)
                #pragma unroll
                for (int e = 0; e < 4; e++) acc[mi][ni][e] = 0.0f;

        for (int kt = 0; kt < KTILES; kt++) {
            const int ktg = iter * KTILES + kt;
            asm volatile("cp.async.wait_group 2;" ::: "memory");
            __syncthreads();
            if (ktg + 3 < NTOT) load_stage(sbase, strip, n_base, ktg + 3, tid);
            cp_commit();

            const __half* xs = smh + (SM_A / 2) + (ktg & 3) * (STAGE_BYTES / 2);
            const __half* bs = smh + (SM_B / 2) + (ktg & 3) * (STAGE_BYTES / 2);

            uint32_t a[2][2][4], b[2][8][2];
            load_frags(xs, bs, 0, wm, wn, grp, tig, a[0], b[0]);
            #pragma unroll
            for (int kk4 = 0; kk4 < 4; kk4++) {       // 4 x k16 steps
                const int cur = kk4 & 1;
                if (kk4 < 3)
                    load_frags(xs, bs, (kk4 + 1) * 16, wm, wn, grp, tig, a[cur ^ 1], b[cur ^ 1]);
                #pragma unroll
                for (int mi = 0; mi < 2; mi++)
                    #pragma unroll
                    for (int ni = 0; ni < 8; ni++)
                        asm volatile(
                            "mma.sync.aligned.m16n8k16.row.col.f32.f16.f16.f32 "
                            "{%0,%1,%2,%3},{%4,%5,%6,%7},{%8,%9},{%0,%1,%2,%3};"
                            : "+f"(acc[mi][ni][0]), "+f"(acc[mi][ni][1]),
                              "+f"(acc[mi][ni][2]), "+f"(acc[mi][ni][3])
                            : "r"(a[cur][mi][0]), "r"(a[cur][mi][1]),
                              "r"(a[cur][mi][2]), "r"(a[cur][mi][3]),
                              "r"(b[cur][ni][0]), "r"(b[cur][ni][1]));
            }
        }

        // ---- register epilogue: gate + pair-combine (shfl_xor 4) + compose ----
        const float t = (float)(strip * TSTRIP + iter * 2 + tp) * (1.0f / 2048.0f);
        float rt[8];
        #pragma unroll
        for (int ni = 0; ni < 8; ni++)
            rt[ni] = 1.0f + tanha(0.5f * (t * rv[ni] + rbv[ni]));   // 2*sigmoid(v)

        #pragma unroll
        for (int mi = 0; mi < 2; mi++)
            #pragma unroll
            for (int ni = 0; ni < 8; ni++)
                #pragma unroll
                for (int hl = 0; hl < 2; hl++) {
                    float zg = acc[mi][ni][hl * 2 + 0];
                    float zh = acc[mi][ni][hl * 2 + 1];
                    float G = rt[ni] * (0.5f + 0.5f * tanha(0.5f * (zg + gbv[ni])));
                    float H = rt[ni] * tanha(zh + hbv[ni]);
                    float Gp = __shfl_xor_sync(0xffffffffu, G, 4);
                    float Hp = __shfl_xor_sync(0xffffffffu, H, 4);
                    float A2 = Gp * G;
                    float B2 = Gp * H + Hp;
                    sB[mi][hl][ni] = A2 * sB[mi][hl][ni] + B2;
                    sA[mi][hl][ni] *= A2;
                }
    }

    asm volatile("cp.async.wait_group 0;" ::: "memory");

    // ---- write strip transform (tp==0 lanes own valid state) ----
    if (tp == 0) {
        #pragma unroll
        for (int mi = 0; mi < 2; mi++)
            #pragma unroll
            for (int hl = 0; hl < 2; hl++)
                #pragma unroll
                for (int ni = 0; ni < 8; ni++) {
                    int bb = (wm >> 1) + mi * 8 + hl * 4 + (grp >> 1);
                    int o  = o_base + (wn >> 1) + ni * 4 + tig;
                    size_t gi = (size_t)(strip * Bdim + bb) * Odim + o;
                    g_As[gi] = sA[mi][hl][ni];
                    g_Bs[gi] = sB[mi][hl][ni];
                }
    }
}

// ---------------- strip combine ----------------
__global__ void rnn_combine(float* __restrict__ out)
{
    int idx = blockIdx.x * 256 + threadIdx.x;   // = b*512 + o
    float y = 0.0f;
    #pragma unroll 8
    for (int s = 0; s < NSTRIPS; s++)
        y = g_As[s * (Bdim * Odim) + idx] * y + g_Bs[s * (Bdim * Odim) + idx];
    out[idx] = y;
}

extern "C" void kernel_launch(void* const* d_in, const int* in_sizes, int n_in,
                              void* d_out, int out_size)
{
    const float* x  = (const float*)d_in[0];
    const float* g  = (const float*)d_in[1];
    const float* gb = (const float*)d_in[2];
    const float* h  = (const float*)d_in[3];
    const float* hb = (const float*)d_in[4];
    const float* r  = (const float*)d_in[5];
    const float* rb = (const float*)d_in[6];

    cudaFuncSetAttribute((const void*)rnn_gemm_scan,
                         cudaFuncAttributeMaxDynamicSharedMemorySize, SM_TOTAL);

    prep_x<<<(Tdim * Bdim * Kdim) / (256 * 4), 256>>>(x);
    prep_w<<<dim3(16, 16, 2), dim3(32, 8)>>>(g, h);
    rnn_gemm_scan<<<dim3(8, NSTRIPS), NTHREADS, SM_TOTAL>>>(gb, hb, r, rb);
    rnn_combine<<<(Bdim * Odim) / 256, 256>>>((float*)d_out);
}

// round 16
// speedup vs baseline: 2.0210x; 1.0121x over previous
#include <cuda_runtime.h>
#include <cuda_fp16.h>
#include <cstdint>

// ---------------- problem dims ----------------
#define Tdim 2048
#define Bdim 64
#define Kdim 512
#define Odim 512

// ---------------- tiling ----------------
#define TSTRIP 16            // timesteps per strip (CTA)
#define NSTRIPS 128          // 2048/16
#define MITERS 8             // 2 timesteps (=128 M rows) per iter
#define KT 64                // K elements per stage
#define KTILES 8             // 512/64
#define NTOT (MITERS*KTILES) // 64 stages per CTA
#define STRA 72              // A stage row stride in f32 (64 + 8 pad) = 288B
#define STRB 72              // B stage row stride in halves (64 + 8 pad) = 144B
#define STAGE_A_BYTES (128*STRA*4)   // 36864
#define STAGE_B_BYTES (128*STRB*2)   // 18432
#define NSTAGE 4
#define NTHREADS 256

// smem layout (bytes)
#define SM_A 0
#define SM_B (NSTAGE*STAGE_A_BYTES)                     // 147456
#define SM_TOTAL (SM_B + NSTAGE*STAGE_B_BYTES)          // 221184

// ---------------- device scratch ----------------
__device__ __half g_wTh[2 * Odim * Kdim];               // K-major interleaved weights, n=2o+s
__device__ float  g_As[NSTRIPS * Bdim * Odim];
__device__ float  g_Bs[NSTRIPS * Bdim * Odim];

// ---------------- helpers ----------------
__device__ __forceinline__ uint32_t smem_u32(const void* p) {
    uint32_t a;
    asm("{ .reg .u64 t; cvta.to.shared.u64 t, %1; cvt.u32.u64 %0, t; }" : "=r"(a) : "l"(p));
    return a;
}
__device__ __forceinline__ void cp16(uint32_t dst, const void* src) {
    asm volatile("cp.async.cg.shared.global [%0], [%1], 16;" :: "r"(dst), "l"(src));
}
__device__ __forceinline__ void cp_commit() { asm volatile("cp.async.commit_group;" ::: "memory"); }
__device__ __forceinline__ float tanha(float x) {
    float y; asm("tanh.approx.f32 %0, %1;" : "=f"(y) : "f"(x)); return y;
}
__device__ __forceinline__ uint32_t ldh2(const __half* p) {
    return *reinterpret_cast<const uint32_t*>(p);
}
// load 2 consecutive f32 from smem, convert to packed half2
__device__ __forceinline__ uint32_t ldf2h(const float* p) {
    float2 v = *reinterpret_cast<const float2*>(p);
    __half2 h = __floats2half2_rn(v.x, v.y);
    return *reinterpret_cast<uint32_t*>(&h);
}

// ---------------- prep: g,h -> interleaved K-major fp16 g_wTh ----------------
__global__ void prep_w(const float* __restrict__ g, const float* __restrict__ h)
{
    __shared__ float t[32][33];
    const int s = blockIdx.z;
    const float* src = s ? h : g;
    const int ob = blockIdx.x * 32, kb = blockIdx.y * 32;
    #pragma unroll
    for (int i = 0; i < 32; i += 8)
        t[threadIdx.y + i][threadIdx.x] = src[(size_t)(kb + threadIdx.y + i) * Odim + ob + threadIdx.x];
    __syncthreads();
    #pragma unroll
    for (int i = 0; i < 32; i += 8)
        g_wTh[(size_t)(2 * (ob + threadIdx.y + i) + s) * Kdim + kb + threadIdx.x] =
            __float2half_rn(t[threadIdx.x][threadIdx.y + i]);
}

// ---------------- stage loader ----------------
// A: f32 direct from x, 128 rows x 64 f32 = 2048 x 16B chunks
// B: fp16 weights,      128 rows x 64 h   = 1024 x 16B chunks
__device__ __forceinline__ void load_stage(uint32_t sbase, const float* __restrict__ x,
                                           int strip, int n_base, int ktg, int tid)
{
    const int stage = ktg & 3;
    const int iter = ktg >> 3, kt = ktg & 7;
    const int kbase = kt * KT;
    const int t0 = strip * TSTRIP + iter * 2;
    const uint32_t aB = sbase + SM_A + stage * STAGE_A_BYTES;
    const uint32_t bB = sbase + SM_B + stage * STAGE_B_BYTES;
    #pragma unroll
    for (int j = 0; j < 8; j++) {                 // A rows: row = 2b+tp
        int c = tid + NTHREADS * j;
        int row = c >> 4, seg = c & 15;           // 16 chunks of 4 f32 per row
        int m = (t0 + (row & 1)) * Bdim + (row >> 1);
        cp16(aB + row * (STRA * 4) + seg * 16,
             x + (size_t)m * Kdim + kbase + seg * 4);
    }
    #pragma unroll
    for (int j = 0; j < 4; j++) {                 // B rows: interleaved (G,H) cols
        int c = tid + NTHREADS * j;
        int row = c >> 3, seg = c & 7;
        cp16(bB + row * (STRB * 2) + seg * 16,
             g_wTh + (size_t)(n_base + row) * Kdim + kbase + seg * 8);
    }
}

// ---------------- fragment loader ----------------
// A from f32 smem (convert), B from fp16 smem. Bank-conflict-free:
//  A: LDS.64, banks (8*grp + 2*tig) mod 32 distinct per 16-lane phase
//  B: LDS.32, banks (4*grp + ...) distinct as before
__device__ __forceinline__ void load_frags(const float* __restrict__ xs,
                                           const __half* __restrict__ bs, int kk,
                                           int wm, int wn, int grp, int tig,
                                           uint32_t a[2][4], uint32_t b[8][2])
{
    #pragma unroll
    for (int mi = 0; mi < 2; mi++) {
        int r0 = wm + mi * 16 + grp;
        a[mi][0] = ldf2h(xs + r0 * STRA + kk + tig * 2);
        a[mi][1] = ldf2h(xs + (r0 + 8) * STRA + kk + tig * 2);
        a[mi][2] = ldf2h(xs + r0 * STRA + kk + tig * 2 + 8);
        a[mi][3] = ldf2h(xs + (r0 + 8) * STRA + kk + tig * 2 + 8);
    }
    #pragma unroll
    for (int ni = 0; ni < 8; ni++) {
        int n = wn + ni * 8 + grp;
        b[ni][0] = ldh2(bs + n * STRB + kk + tig * 2);
        b[ni][1] = ldh2(bs + n * STRB + kk + tig * 2 + 8);
    }
}

// ---------------- main kernel ----------------
__global__ void __launch_bounds__(NTHREADS, 1)
rnn_gemm_scan(const float* __restrict__ x,
              const float* __restrict__ gb, const float* __restrict__ hb,
              const float* __restrict__ r,  const float* __restrict__ rb)
{
    extern __shared__ float smf[];
    const uint32_t sbase = smem_u32(smf);
    const int tid = threadIdx.x, lane = tid & 31, wid = tid >> 5;
    const int o_base = blockIdx.x * 64;       // 64 outputs per CTA (N=128 interleaved)
    const int strip  = blockIdx.y;
    const int wm = (wid & 3) * 32;            // 4 warps in M
    const int wn = (wid >> 2) * 64;           // 2 warps in N
    const int grp = lane >> 2, tig = lane & 3;
    const int tp = grp & 1;                   // timestep parity of this thread's rows

    float gbv[8], hbv[8], rv[8], rbv[8];
    #pragma unroll
    for (int ni = 0; ni < 8; ni++) {
        int o = o_base + (wn >> 1) + ni * 4 + tig;
        gbv[ni] = gb[o]; hbv[ni] = hb[o]; rv[ni] = r[o]; rbv[ni] = rb[o];
    }
    // register-resident scan state [mi][hl][ni]
    float sA[2][2][8], sB[2][2][8];
    #pragma unroll
    for (int mi = 0; mi < 2; mi++)
        #pragma unroll
        for (int hl = 0; hl < 2; hl++)
            #pragma unroll
            for (int ni = 0; ni < 8; ni++) { sA[mi][hl][ni] = 1.0f; sB[mi][hl][ni] = 0.0f; }

    const int n_base = o_base * 2;

    load_stage(sbase, x, strip, n_base, 0, tid); cp_commit();
    load_stage(sbase, x, strip, n_base, 1, tid); cp_commit();
    load_stage(sbase, x, strip, n_base, 2, tid); cp_commit();

    for (int iter = 0; iter < MITERS; iter++) {
        float acc[2][8][4];
        #pragma unroll
        for (int mi = 0; mi < 2; mi++)
            #pragma unroll
            for (int ni = 0; ni < 8; ni++)
                #pragma unroll
                for (int e = 0; e < 4; e++) acc[mi][ni][e] = 0.0f;

        for (int kt = 0; kt < KTILES; kt++) {
            const int ktg = iter * KTILES + kt;
            asm volatile("cp.async.wait_group 2;" ::: "memory");
            __syncthreads();
            if (ktg + 3 < NTOT) load_stage(sbase, x, strip, n_base, ktg + 3, tid);
            cp_commit();

            const float*  xs = smf + (ktg & 3) * (STAGE_A_BYTES / 4);
            const __half* bs = reinterpret_cast<const __half*>(smf + SM_B / 4)
                               + (ktg & 3) * (STAGE_B_BYTES / 2);

            uint32_t a[2][2][4], b[2][8][2];
            load_frags(xs, bs, 0, wm, wn, grp, tig, a[0], b[0]);
            #pragma unroll
            for (int kk4 = 0; kk4 < 4; kk4++) {       // 4 x k16 steps
                const int cur = kk4 & 1;
                if (kk4 < 3)
                    load_frags(xs, bs, (kk4 + 1) * 16, wm, wn, grp, tig, a[cur ^ 1], b[cur ^ 1]);
                #pragma unroll
                for (int mi = 0; mi < 2; mi++)
                    #pragma unroll
                    for (int ni = 0; ni < 8; ni++)
                        asm volatile(
                            "mma.sync.aligned.m16n8k16.row.col.f32.f16.f16.f32 "
                            "{%0,%1,%2,%3},{%4,%5,%6,%7},{%8,%9},{%0,%1,%2,%3};"
                            : "+f"(acc[mi][ni][0]), "+f"(acc[mi][ni][1]),
                              "+f"(acc[mi][ni][2]), "+f"(acc[mi][ni][3])
                            : "r"(a[cur][mi][0]), "r"(a[cur][mi][1]),
                              "r"(a[cur][mi][2]), "r"(a[cur][mi][3]),
                              "r"(b[cur][ni][0]), "r"(b[cur][ni][1]));
            }
        }

        // ---- register epilogue: gate + pair-combine (shfl_xor 4) + compose ----
        const float t = (float)(strip * TSTRIP + iter * 2 + tp) * (1.0f / 2048.0f);
        float rt[8];
        #pragma unroll
        for (int ni = 0; ni < 8; ni++)
            rt[ni] = 1.0f + tanha(0.5f * (t * rv[ni] + rbv[ni]));   // 2*sigmoid(v)

        #pragma unroll
        for (int mi = 0; mi < 2; mi++)
            #pragma unroll
            for (int ni = 0; ni < 8; ni++)
                #pragma unroll
                for (int hl = 0; hl < 2; hl++) {
                    float zg = acc[mi][ni][hl * 2 + 0];
                    float zh = acc[mi][ni][hl * 2 + 1];
                    float G = rt[ni] * (0.5f + 0.5f * tanha(0.5f * (zg + gbv[ni])));
                    float H = rt[ni] * tanha(zh + hbv[ni]);
                    float Gp = __shfl_xor_sync(0xffffffffu, G, 4);
                    float Hp = __shfl_xor_sync(0xffffffffu, H, 4);
                    float A2 = Gp * G;
                    float B2 = Gp * H + Hp;
                    sB[mi][hl][ni] = A2 * sB[mi][hl][ni] + B2;
                    sA[mi][hl][ni] *= A2;
                }
    }

    asm volatile("cp.async.wait_group 0;" ::: "memory");

    // ---- write strip transform (tp==0 lanes own valid state) ----
    if (tp == 0) {
        #pragma unroll
        for (int mi = 0; mi < 2; mi++)
            #pragma unroll
            for (int hl = 0; hl < 2; hl++)
                #pragma unroll
                for (int ni = 0; ni < 8; ni++) {
                    int bb = (wm >> 1) + mi * 8 + hl * 4 + (grp >> 1);
                    int o  = o_base + (wn >> 1) + ni * 4 + tig;
                    size_t gi = (size_t)(strip * Bdim + bb) * Odim + o;
                    g_As[gi] = sA[mi][hl][ni];
                    g_Bs[gi] = sB[mi][hl][ni];
                }
    }
}

// ---------------- strip combine ----------------
__global__ void rnn_combine(float* __restrict__ out)
{
    int idx = blockIdx.x * 256 + threadIdx.x;   // = b*512 + o
    float y = 0.0f;
    #pragma unroll 8
    for (int s = 0; s < NSTRIPS; s++)
        y = g_As[s * (Bdim * Odim) + idx] * y + g_Bs[s * (Bdim * Odim) + idx];
    out[idx] = y;
}

extern "C" void kernel_launch(void* const* d_in, const int* in_sizes, int n_in,
                              void* d_out, int out_size)
{
    const float* x  = (const float*)d_in[0];
    const float* g  = (const float*)d_in[1];
    const float* gb = (const float*)d_in[2];
    const float* h  = (const float*)d_in[3];
    const float* hb = (const float*)d_in[4];
    const float* r  = (const float*)d_in[5];
    const float* rb = (const float*)d_in[6];

    cudaFuncSetAttribute((const void*)rnn_gemm_scan,
                         cudaFuncAttributeMaxDynamicSharedMemorySize, SM_TOTAL);

    prep_w<<<dim3(16, 16, 2), dim3(32, 8)>>>(g, h);
    rnn_gemm_scan<<<dim3(8, NSTRIPS), NTHREADS, SM_TOTAL>>>(x, gb, hb, r, rb);
    rnn_combine<<<(Bdim * Odim) / 256, 256>>>((float*)d_out);
}